// round 2
// baseline (speedup 1.0000x reference)
#include <cuda_runtime.h>
#include <cstdint>

#define N_REFLNS 2000000
#define N_IMAGES 8192
#define N_RAC    1000000
#define MC       8
#define D_META   16
#define HIDDEN   32
#define LOG_2PI_F 1.8378770664093453f

// ---------------- scratch (static device globals; no allocation) ----------------
__device__ float4 g_zT[N_RAC * 2];       // z transposed: (N_RAC, 8) as 2x float4 per row
__device__ float  g_img_sum[N_IMAGES];
__device__ float  g_img_cnt[N_IMAGES];
__device__ float  g_kl_sum;

// ---------------- packed fp32x2 FMA (sm_103a; ptxas won't auto-emit) ------------
__device__ __forceinline__ float2 ffma2(float2 a, float2 b, float2 c) {
    float2 d;
    asm("{\n\t"
        ".reg .b64 ra, rb, rc, rd;\n\t"
        "mov.b64 ra, {%2,%3};\n\t"
        "mov.b64 rb, {%4,%5};\n\t"
        "mov.b64 rc, {%6,%7};\n\t"
        "fma.rn.f32x2 rd, ra, rb, rc;\n\t"
        "mov.b64 {%0,%1}, rd;\n\t"
        "}"
        : "=f"(d.x), "=f"(d.y)
        : "f"(a.x), "f"(a.y), "f"(b.x), "f"(b.y), "f"(c.x), "f"(c.y));
    return d;
}

__device__ __forceinline__ float softplus_f(float x) {
    // softplus(x) = max(x,0) + log1p(exp(-|x|)); fast log1p with small-t fallback
    float ax = fabsf(x);
    float t  = __expf(-ax);
    float l  = (t > 0.0078125f) ? __logf(1.0f + t) : fmaf(-0.5f * t, t, t);
    return fmaxf(x, 0.0f) + l;
}

// ---------------- kernel 0: zero accumulators ----------------
__global__ void init_kernel() {
    int i = blockIdx.x * blockDim.x + threadIdx.x;
    if (i < N_IMAGES) { g_img_sum[i] = 0.0f; g_img_cnt[i] = 0.0f; }
    if (i == 0) g_kl_sum = 0.0f;
}

// ---------------- kernel 1: z transpose + KL reduction ----------------
__global__ __launch_bounds__(256) void zkl_kernel(const float* __restrict__ q_loc,
                                                  const float* __restrict__ q_ls,
                                                  const float* __restrict__ eps) {
    int m = blockIdx.x * 256 + threadIdx.x;
    float kl = 0.0f;
    if (m < N_RAC) {
        float loc = q_loc[m];
        float ls  = q_ls[m];
        float s   = __expf(ls);
        kl = fmaf(0.5f, fmaf(s, s, fmaf(loc, loc, -1.0f)), -ls);
        float z[8];
#pragma unroll
        for (int c = 0; c < 8; c++)
            z[c] = fmaf(s, eps[(size_t)c * N_RAC + m], loc);
        g_zT[2 * m]     = make_float4(z[0], z[1], z[2], z[3]);
        g_zT[2 * m + 1] = make_float4(z[4], z[5], z[6], z[7]);
    }
    // block reduce kl -> atomic
#pragma unroll
    for (int off = 16; off; off >>= 1)
        kl += __shfl_down_sync(0xffffffffu, kl, off);
    __shared__ float wsum[8];
    int lane = threadIdx.x & 31, wid = threadIdx.x >> 5;
    if (lane == 0) wsum[wid] = kl;
    __syncthreads();
    if (threadIdx.x == 0) {
        float t = 0.0f;
#pragma unroll
        for (int i = 0; i < 8; i++) t += wsum[i];
        atomicAdd(&g_kl_sum, t);
    }
}

// ---------------- kernel 2: per-reflection MLP + likelihood ----------------
__global__ __launch_bounds__(256) void refl_kernel(const float* __restrict__ metadata,
                                                   const float* __restrict__ W1,
                                                   const float* __restrict__ b1,
                                                   const float* __restrict__ W2,
                                                   const float* __restrict__ b2,
                                                   const float* __restrict__ iobs,
                                                   const float* __restrict__ sigiobs,
                                                   const int*   __restrict__ image_id,
                                                   const int*   __restrict__ miller_id,
                                                   float*       __restrict__ out) {
    __shared__ float2 sW1[256];  // [i*16 + j]  (j = pair of hidden cols)
    __shared__ float2 sb1[16];
    __shared__ float2 sW2[128];  // [i*4 + k]   (k = pair of MC cols)
    __shared__ float2 sb2[4];

    int tid = threadIdx.x;
    { sW1[tid] = ((const float2*)W1)[tid]; }
    if (tid < 128) sW2[tid] = ((const float2*)W2)[tid];
    if (tid < 16)  sb1[tid] = ((const float2*)b1)[tid];
    if (tid < 4)   sb2[tid] = ((const float2*)b2)[tid];
    __syncthreads();

    int r = blockIdx.x * 256 + tid;
    int img = -1;
    float ll_sum = 0.0f;

    if (r < N_REFLNS) {
        // metadata row (16 floats, coalesced float4 stream)
        const float4* mp = (const float4*)(metadata + (size_t)r * D_META);
        float4 m0 = mp[0], m1 = mp[1], m2 = mp[2], m3 = mp[3];
        float m[16] = {m0.x, m0.y, m0.z, m0.w, m1.x, m1.y, m1.z, m1.w,
                       m2.x, m2.y, m2.z, m2.w, m3.x, m3.y, m3.z, m3.w};

        // layer 1: h = relu(meta @ W1 + b1), 16 packed accumulators
        float2 h[16];
#pragma unroll
        for (int j = 0; j < 16; j++) h[j] = sb1[j];
#pragma unroll
        for (int i = 0; i < 16; i++) {
            float2 mi = make_float2(m[i], m[i]);
#pragma unroll
            for (int j = 0; j < 16; j++)
                h[j] = ffma2(mi, sW1[i * 16 + j], h[j]);
        }

        // layer 2: p = h @ W2 + b2 (relu fused into operand)
        float2 p[4];
#pragma unroll
        for (int k = 0; k < 4; k++) p[k] = sb2[k];
#pragma unroll
        for (int i = 0; i < 16; i++) {
            float hx = fmaxf(h[i].x, 0.0f);
            float hy = fmaxf(h[i].y, 0.0f);
            float2 ax = make_float2(hx, hx);
            float2 ay = make_float2(hy, hy);
#pragma unroll
            for (int k = 0; k < 4; k++)
                p[k] = ffma2(ax, sW2[(2 * i) * 4 + k], p[k]);
#pragma unroll
            for (int k = 0; k < 4; k++)
                p[k] = ffma2(ay, sW2[(2 * i + 1) * 4 + k], p[k]);
        }

        float scale[8];
#pragma unroll
        for (int k = 0; k < 4; k++) {
            scale[2 * k]     = softplus_f(p[k].x);
            scale[2 * k + 1] = softplus_f(p[k].y);
        }

        // gather z samples: one contiguous 32B read (L2-resident table)
        int mid = miller_id[r];
        float4 f0 = g_zT[2 * mid];
        float4 f1 = g_zT[2 * mid + 1];
        float f[8] = {f0.x, f0.y, f0.z, f0.w, f1.x, f1.y, f1.z, f1.w};

        float io  = iobs[r];
        float sg  = sigiobs[r];
        float inv = 1.0f / sg;

        float sum_i = 0.0f, ss = 0.0f;
#pragma unroll
        for (int c = 0; c < 8; c++) {
            float ip = f[c] * f[c] * scale[c];
            sum_i += ip;
            float rr = (ip - io) * inv;
            ss = fmaf(rr, rr, ss);
        }
        out[r] = sum_i * 0.125f;
        ll_sum = fmaf(-0.5f, ss, -8.0f * (__logf(sg) + 0.5f * LOG_2PI_F));
        img = image_id[r];
    }

    // warp-segmented aggregation (image_id sorted -> contiguous equal segments)
    unsigned mask = __match_any_sync(0xffffffffu, img);
    int lane = tid & 31;
    int hi   = 31 - __clz(mask);
    float v  = ll_sum;
#pragma unroll
    for (int off = 1; off < 32; off <<= 1) {
        float o = __shfl_down_sync(0xffffffffu, v, off);
        if (lane + off <= hi) v += o;
    }
    if (img >= 0 && lane == (__ffs(mask) - 1)) {
        atomicAdd(&g_img_sum[img], v);
        atomicAdd(&g_img_cnt[img], (float)__popc(mask));
    }
}

// ---------------- kernel 3: finalize scalars ----------------
__global__ __launch_bounds__(256) void finalize_kernel(float* __restrict__ out) {
    float acc = 0.0f;
    for (int i = threadIdx.x; i < N_IMAGES; i += 256)
        acc += g_img_sum[i] / fmaxf(g_img_cnt[i], 1.0f);
#pragma unroll
    for (int off = 16; off; off >>= 1)
        acc += __shfl_down_sync(0xffffffffu, acc, off);
    __shared__ float wsum[8];
    int lane = threadIdx.x & 31, wid = threadIdx.x >> 5;
    if (lane == 0) wsum[wid] = acc;
    __syncthreads();
    if (threadIdx.x == 0) {
        float t = 0.0f;
#pragma unroll
        for (int i = 0; i < 8; i++) t += wsum[i];
        // ll_img = per_img / max(cnt,1) / MC ; neg mean over images
        out[N_REFLNS]     = -(t / (float)MC) / (float)N_IMAGES;
        out[N_REFLNS + 1] = g_kl_sum * (1.0f / (float)N_RAC);
    }
}

// ---------------- launch ----------------
extern "C" void kernel_launch(void* const* d_in, const int* in_sizes, int n_in,
                              void* d_out, int out_size) {
    const float* q_loc     = (const float*)d_in[0];
    const float* q_ls      = (const float*)d_in[1];
    const float* eps       = (const float*)d_in[2];
    const float* metadata  = (const float*)d_in[3];
    const float* W1        = (const float*)d_in[4];
    const float* b1        = (const float*)d_in[5];
    const float* W2        = (const float*)d_in[6];
    const float* b2        = (const float*)d_in[7];
    const float* iobs      = (const float*)d_in[8];
    const float* sigiobs   = (const float*)d_in[9];
    const int*   image_id  = (const int*)d_in[10];
    const int*   miller_id = (const int*)d_in[11];
    float* out = (float*)d_out;

    init_kernel<<<(N_IMAGES + 255) / 256, 256>>>();
    zkl_kernel<<<(N_RAC + 255) / 256, 256>>>(q_loc, q_ls, eps);
    refl_kernel<<<(N_REFLNS + 255) / 256, 256>>>(metadata, W1, b1, W2, b2,
                                                 iobs, sigiobs, image_id, miller_id, out);
    finalize_kernel<<<1, 256>>>(out);
}

// round 3
// speedup vs baseline: 1.2729x; 1.2729x over previous
#include <cuda_runtime.h>
#include <cstdint>

#define N_REFLNS 2000000
#define N_IMAGES 8192
#define N_RAC    1000000
#define MC       8
#define D_META   16
#define HIDDEN   32
#define LOG_2PI_F 1.8378770664093453f

// ---------------- scratch (static device globals; no allocation) ----------------
__device__ float4 g_zT[N_RAC * 2];       // z transposed: (N_RAC, 8) as 2x float4 per row
__device__ float  g_img_sum[N_IMAGES];
__device__ float  g_img_cnt[N_IMAGES];
__device__ float  g_kl_sum;
__device__ float  g_ll_total;
__device__ unsigned g_done;

// ---------------- packed fp32x2 FMA (sm_103a; ptxas won't auto-emit) ------------
__device__ __forceinline__ float2 ffma2(float2 a, float2 b, float2 c) {
    float2 d;
    asm("{\n\t"
        ".reg .b64 ra, rb, rc, rd;\n\t"
        "mov.b64 ra, {%2,%3};\n\t"
        "mov.b64 rb, {%4,%5};\n\t"
        "mov.b64 rc, {%6,%7};\n\t"
        "fma.rn.f32x2 rd, ra, rb, rc;\n\t"
        "mov.b64 {%0,%1}, rd;\n\t"
        "}"
        : "=f"(d.x), "=f"(d.y)
        : "f"(a.x), "f"(a.y), "f"(b.x), "f"(b.y), "f"(c.x), "f"(c.y));
    return d;
}

__device__ __forceinline__ float2 bc2(float x) { return make_float2(x, x); }
__device__ __forceinline__ float2 f2(float x, float y) { return make_float2(x, y); }

__device__ __forceinline__ float softplus_f(float x) {
    float ax = fabsf(x);
    float t  = __expf(-ax);
    float l  = (t > 0.0078125f) ? __logf(1.0f + t) : fmaf(-0.5f * t, t, t);
    return fmaxf(x, 0.0f) + l;
}

// ---------------- kernel 0: zero accumulators ----------------
__global__ void init_kernel() {
    int i = blockIdx.x * blockDim.x + threadIdx.x;
    if (i < N_IMAGES) { g_img_sum[i] = 0.0f; g_img_cnt[i] = 0.0f; }
    if (i == 0) { g_kl_sum = 0.0f; g_ll_total = 0.0f; g_done = 0u; }
}

// ---------------- kernel 1: z transpose + KL reduction ----------------
__global__ __launch_bounds__(256) void zkl_kernel(const float* __restrict__ q_loc,
                                                  const float* __restrict__ q_ls,
                                                  const float* __restrict__ eps) {
    int m = blockIdx.x * 256 + threadIdx.x;
    float kl = 0.0f;
    if (m < N_RAC) {
        float loc = q_loc[m];
        float ls  = q_ls[m];
        float s   = __expf(ls);
        kl = fmaf(0.5f, fmaf(s, s, fmaf(loc, loc, -1.0f)), -ls);
        float z[8];
#pragma unroll
        for (int c = 0; c < 8; c++)
            z[c] = fmaf(s, eps[(size_t)c * N_RAC + m], loc);
        g_zT[2 * m]     = make_float4(z[0], z[1], z[2], z[3]);
        g_zT[2 * m + 1] = make_float4(z[4], z[5], z[6], z[7]);
    }
#pragma unroll
    for (int off = 16; off; off >>= 1)
        kl += __shfl_down_sync(0xffffffffu, kl, off);
    __shared__ float wsum[8];
    int lane = threadIdx.x & 31, wid = threadIdx.x >> 5;
    if (lane == 0) wsum[wid] = kl;
    __syncthreads();
    if (threadIdx.x == 0) {
        float t = 0.0f;
#pragma unroll
        for (int i = 0; i < 8; i++) t += wsum[i];
        atomicAdd(&g_kl_sum, t);
    }
}

// ---------------- per-reflection epilogue ----------------
__device__ __forceinline__ void epilogue(const float2 p[4], int r, bool valid,
                                         const float* __restrict__ iobs,
                                         const float* __restrict__ sigiobs,
                                         const int* __restrict__ image_id,
                                         const int* __restrict__ miller_id,
                                         float* __restrict__ out,
                                         float& ll, int& img) {
    ll = 0.0f; img = -1;
    if (!valid) return;
    float scale[8];
#pragma unroll
    for (int k = 0; k < 4; k++) {
        scale[2 * k]     = softplus_f(p[k].x);
        scale[2 * k + 1] = softplus_f(p[k].y);
    }
    int mid = miller_id[r];
    float4 f0 = g_zT[2 * mid];
    float4 f1 = g_zT[2 * mid + 1];
    float f[8] = {f0.x, f0.y, f0.z, f0.w, f1.x, f1.y, f1.z, f1.w};

    float io  = iobs[r];
    float sg  = sigiobs[r];
    float inv = 1.0f / sg;

    float sum_i = 0.0f, ss = 0.0f;
#pragma unroll
    for (int c = 0; c < 8; c++) {
        float ip = f[c] * f[c] * scale[c];
        sum_i += ip;
        float rr = (ip - io) * inv;
        ss = fmaf(rr, rr, ss);
    }
    out[r] = sum_i * 0.125f;
    ll = fmaf(-0.5f, ss, -8.0f * (__logf(sg) + 0.5f * LOG_2PI_F));
    img = image_id[r];
}

// segmented warp reduce + atomic (image_id sorted -> contiguous segments)
__device__ __forceinline__ void seg_atomic(float ll, int img, int lane) {
    unsigned mask = __match_any_sync(0xffffffffu, img);
    int hi = 31 - __clz(mask);
    float v = ll;
#pragma unroll
    for (int off = 1; off < 32; off <<= 1) {
        float o = __shfl_down_sync(0xffffffffu, v, off);
        if (lane + off <= hi) v += o;
    }
    if (img >= 0 && lane == (__ffs(mask) - 1)) {
        atomicAdd(&g_img_sum[img], v);
        atomicAdd(&g_img_cnt[img], (float)__popc(mask));
    }
}

// ---------------- kernel 2: MLP + likelihood, 2 reflections/thread ----------------
__global__ __launch_bounds__(128) void refl_kernel(const float* __restrict__ metadata,
                                                   const float* __restrict__ W1,
                                                   const float* __restrict__ b1,
                                                   const float* __restrict__ W2,
                                                   const float* __restrict__ b2,
                                                   const float* __restrict__ iobs,
                                                   const float* __restrict__ sigiobs,
                                                   const int*   __restrict__ image_id,
                                                   const int*   __restrict__ miller_id,
                                                   float*       __restrict__ out) {
    __shared__ float4 sW1[128];  // W1 row i (32 floats): idx = i*8 + q, covers hidden 4q..4q+3
    __shared__ float4 sW2[64];   // W2 row u (8 floats):  idx = u*2 + t
    __shared__ float2 sb1[16];
    __shared__ float2 sb2[4];

    int tid = threadIdx.x;
    sW1[tid] = ((const float4*)W1)[tid];
    if (tid < 64) sW2[tid] = ((const float4*)W2)[tid];
    if (tid < 16) sb1[tid] = ((const float2*)b1)[tid];
    if (tid < 4)  sb2[tid] = ((const float2*)b2)[tid];
    __syncthreads();

    int rA = blockIdx.x * 256 + tid;
    int rB = rA + 128;
    bool vA = rA < N_REFLNS;
    bool vB = rB < N_REFLNS;

    float2 hA[16], hB[16];
#pragma unroll
    for (int j = 0; j < 16; j++) { hA[j] = sb1[j]; hB[j] = sb1[j]; }

    const float4* mpA = (const float4*)(metadata + (size_t)rA * D_META);
    const float4* mpB = (const float4*)(metadata + (size_t)rB * D_META);
    const float4 z4 = make_float4(0.f, 0.f, 0.f, 0.f);

    // layer 1: weights loaded once from shared, used for both reflections
#pragma unroll
    for (int c = 0; c < 4; c++) {
        float4 ma = vA ? mpA[c] : z4;
        float4 mb = vB ? mpB[c] : z4;
        float mav[4] = {ma.x, ma.y, ma.z, ma.w};
        float mbv[4] = {mb.x, mb.y, mb.z, mb.w};
#pragma unroll
        for (int ii = 0; ii < 4; ii++) {
            int i = 4 * c + ii;
            float2 aA = bc2(mav[ii]);
            float2 aB = bc2(mbv[ii]);
#pragma unroll
            for (int q = 0; q < 8; q++) {
                float4 w = sW1[i * 8 + q];
                float2 wlo = f2(w.x, w.y), whi = f2(w.z, w.w);
                hA[2 * q]     = ffma2(aA, wlo, hA[2 * q]);
                hA[2 * q + 1] = ffma2(aA, whi, hA[2 * q + 1]);
                hB[2 * q]     = ffma2(aB, wlo, hB[2 * q]);
                hB[2 * q + 1] = ffma2(aB, whi, hB[2 * q + 1]);
            }
        }
    }

    // layer 2: p = relu(h) @ W2 + b2
    float2 pA[4], pB[4];
#pragma unroll
    for (int k = 0; k < 4; k++) { pA[k] = sb2[k]; pB[k] = sb2[k]; }
#pragma unroll
    for (int up = 0; up < 16; up++) {
        int u0 = 2 * up, u1 = 2 * up + 1;
        float4 w00 = sW2[u0 * 2], w01 = sW2[u0 * 2 + 1];
        float4 w10 = sW2[u1 * 2], w11 = sW2[u1 * 2 + 1];
        float2 w00a = f2(w00.x, w00.y), w00b = f2(w00.z, w00.w);
        float2 w01a = f2(w01.x, w01.y), w01b = f2(w01.z, w01.w);
        float2 w10a = f2(w10.x, w10.y), w10b = f2(w10.z, w10.w);
        float2 w11a = f2(w11.x, w11.y), w11b = f2(w11.z, w11.w);

        float2 xA = bc2(fmaxf(hA[up].x, 0.0f));
        float2 yA = bc2(fmaxf(hA[up].y, 0.0f));
        float2 xB = bc2(fmaxf(hB[up].x, 0.0f));
        float2 yB = bc2(fmaxf(hB[up].y, 0.0f));

        pA[0] = ffma2(xA, w00a, pA[0]); pA[1] = ffma2(xA, w00b, pA[1]);
        pA[2] = ffma2(xA, w01a, pA[2]); pA[3] = ffma2(xA, w01b, pA[3]);
        pA[0] = ffma2(yA, w10a, pA[0]); pA[1] = ffma2(yA, w10b, pA[1]);
        pA[2] = ffma2(yA, w11a, pA[2]); pA[3] = ffma2(yA, w11b, pA[3]);

        pB[0] = ffma2(xB, w00a, pB[0]); pB[1] = ffma2(xB, w00b, pB[1]);
        pB[2] = ffma2(xB, w01a, pB[2]); pB[3] = ffma2(xB, w01b, pB[3]);
        pB[0] = ffma2(yB, w10a, pB[0]); pB[1] = ffma2(yB, w10b, pB[1]);
        pB[2] = ffma2(yB, w11a, pB[2]); pB[3] = ffma2(yB, w11b, pB[3]);
    }

    int lane = tid & 31;
    float llA, llB; int imgA, imgB;
    epilogue(pA, rA, vA, iobs, sigiobs, image_id, miller_id, out, llA, imgA);
    epilogue(pB, rB, vB, iobs, sigiobs, image_id, miller_id, out, llB, imgB);
    seg_atomic(llA, imgA, lane);
    seg_atomic(llB, imgB, lane);
}

// ---------------- kernel 3: parallel finalize (8 blocks, last block writes) -----
__global__ __launch_bounds__(1024) void finalize_kernel(float* __restrict__ out) {
    int i = blockIdx.x * 1024 + threadIdx.x;
    float v = g_img_sum[i] * (1.0f / fmaxf(g_img_cnt[i], 1.0f));
#pragma unroll
    for (int off = 16; off; off >>= 1)
        v += __shfl_down_sync(0xffffffffu, v, off);
    __shared__ float wsum[32];
    int lane = threadIdx.x & 31, wid = threadIdx.x >> 5;
    if (lane == 0) wsum[wid] = v;
    __syncthreads();
    if (wid == 0) {
        float t = wsum[lane];
#pragma unroll
        for (int off = 16; off; off >>= 1)
            t += __shfl_down_sync(0xffffffffu, t, off);
        if (lane == 0) {
            atomicAdd(&g_ll_total, t);
            __threadfence();
            unsigned ticket = atomicAdd(&g_done, 1u);
            if (ticket == gridDim.x - 1) {
                float total = atomicAdd(&g_ll_total, 0.0f);  // fenced read of final sum
                out[N_REFLNS]     = -(total / (float)MC) / (float)N_IMAGES;
                out[N_REFLNS + 1] = g_kl_sum * (1.0f / (float)N_RAC);
            }
        }
    }
}

// ---------------- launch ----------------
extern "C" void kernel_launch(void* const* d_in, const int* in_sizes, int n_in,
                              void* d_out, int out_size) {
    const float* q_loc     = (const float*)d_in[0];
    const float* q_ls      = (const float*)d_in[1];
    const float* eps       = (const float*)d_in[2];
    const float* metadata  = (const float*)d_in[3];
    const float* W1        = (const float*)d_in[4];
    const float* b1        = (const float*)d_in[5];
    const float* W2        = (const float*)d_in[6];
    const float* b2        = (const float*)d_in[7];
    const float* iobs      = (const float*)d_in[8];
    const float* sigiobs   = (const float*)d_in[9];
    const int*   image_id  = (const int*)d_in[10];
    const int*   miller_id = (const int*)d_in[11];
    float* out = (float*)d_out;

    init_kernel<<<(N_IMAGES + 255) / 256, 256>>>();
    zkl_kernel<<<(N_RAC + 255) / 256, 256>>>(q_loc, q_ls, eps);
    refl_kernel<<<(N_REFLNS + 255) / 256, 128>>>(metadata, W1, b1, W2, b2,
                                                 iobs, sigiobs, image_id, miller_id, out);
    finalize_kernel<<<N_IMAGES / 1024, 1024>>>(out);
}

// round 5
// speedup vs baseline: 1.2757x; 1.0022x over previous
#include <cuda_runtime.h>
#include <cstdint>

#define N_REFLNS 2000000
#define N_IMAGES 8192
#define N_RAC    1000000
#define MC       8
#define D_META   16
#define HIDDEN   32
#define LOG_2PI_F 1.8378770664093453f

typedef unsigned long long ull;

// ---------------- scratch (static device globals; no allocation) ----------------
__device__ float4 g_zT[N_RAC * 2];       // z transposed: (N_RAC, 8) as 2x float4 per row
__device__ float  g_img_sum[N_IMAGES];
__device__ float  g_img_cnt[N_IMAGES];
__device__ float  g_kl_sum;
__device__ float  g_ll_total;
__device__ unsigned g_done;

// ------------- packed fp32x2 ops: 64-bit register operands, zero pack movs ------
__device__ __forceinline__ ull ffma2u(ull a, ull b, ull c) {
    ull d;
    asm("fma.rn.f32x2 %0, %1, %2, %3;" : "=l"(d) : "l"(a), "l"(b), "l"(c));
    return d;
}
__device__ __forceinline__ ull bcast2(float x) {
    ull d;
    asm("mov.b64 %0, {%1, %1};" : "=l"(d) : "f"(x));
    return d;
}
__device__ __forceinline__ float2 unpack2(ull v) {
    float2 r;
    asm("mov.b64 {%0, %1}, %2;" : "=f"(r.x), "=f"(r.y) : "l"(v));
    return r;
}

__device__ __forceinline__ float softplus_f(float x) {
    float ax = fabsf(x);
    float t  = __expf(-ax);
    float l  = (t > 0.0078125f) ? __logf(1.0f + t) : fmaf(-0.5f * t, t, t);
    return fmaxf(x, 0.0f) + l;
}

// ---------------- kernel 0: zero accumulators ----------------
__global__ void init_kernel() {
    int i = blockIdx.x * blockDim.x + threadIdx.x;
    if (i < N_IMAGES) { g_img_sum[i] = 0.0f; g_img_cnt[i] = 0.0f; }
    if (i == 0) { g_kl_sum = 0.0f; g_ll_total = 0.0f; g_done = 0u; }
}

// ---------------- kernel 1: z transpose + KL reduction ----------------
__global__ __launch_bounds__(256) void zkl_kernel(const float* __restrict__ q_loc,
                                                  const float* __restrict__ q_ls,
                                                  const float* __restrict__ eps) {
    int m = blockIdx.x * 256 + threadIdx.x;
    float kl = 0.0f;
    if (m < N_RAC) {
        float loc = q_loc[m];
        float ls  = q_ls[m];
        float s   = __expf(ls);
        kl = fmaf(0.5f, fmaf(s, s, fmaf(loc, loc, -1.0f)), -ls);
        float z[8];
#pragma unroll
        for (int c = 0; c < 8; c++)
            z[c] = fmaf(s, eps[(size_t)c * N_RAC + m], loc);
        g_zT[2 * m]     = make_float4(z[0], z[1], z[2], z[3]);
        g_zT[2 * m + 1] = make_float4(z[4], z[5], z[6], z[7]);
    }
#pragma unroll
    for (int off = 16; off; off >>= 1)
        kl += __shfl_down_sync(0xffffffffu, kl, off);
    __shared__ float wsum[8];
    int lane = threadIdx.x & 31, wid = threadIdx.x >> 5;
    if (lane == 0) wsum[wid] = kl;
    __syncthreads();
    if (threadIdx.x == 0) {
        float t = 0.0f;
#pragma unroll
        for (int i = 0; i < 8; i++) t += wsum[i];
        atomicAdd(&g_kl_sum, t);
    }
}

// ---------------- per-reflection epilogue ----------------
__device__ __forceinline__ void epilogue(const ull p[4], int r, bool valid,
                                         const float* __restrict__ iobs,
                                         const float* __restrict__ sigiobs,
                                         const int* __restrict__ image_id,
                                         const int* __restrict__ miller_id,
                                         float* __restrict__ out,
                                         float& ll, int& img) {
    ll = 0.0f; img = -1;
    if (!valid) return;
    float scale[8];
#pragma unroll
    for (int k = 0; k < 4; k++) {
        float2 pk = unpack2(p[k]);
        scale[2 * k]     = softplus_f(pk.x);
        scale[2 * k + 1] = softplus_f(pk.y);
    }
    int mid = miller_id[r];
    float4 f0 = g_zT[2 * mid];
    float4 f1 = g_zT[2 * mid + 1];
    float f[8] = {f0.x, f0.y, f0.z, f0.w, f1.x, f1.y, f1.z, f1.w};

    float io  = iobs[r];
    float sg  = sigiobs[r];
    float inv = 1.0f / sg;

    float sum_i = 0.0f, ss = 0.0f;
#pragma unroll
    for (int c = 0; c < 8; c++) {
        float ip = f[c] * f[c] * scale[c];
        sum_i += ip;
        float rr = (ip - io) * inv;
        ss = fmaf(rr, rr, ss);
    }
    out[r] = sum_i * 0.125f;
    ll = fmaf(-0.5f, ss, -8.0f * (__logf(sg) + 0.5f * LOG_2PI_F));
    img = image_id[r];
}

// segmented warp reduce + atomic (image_id sorted -> contiguous segments)
__device__ __forceinline__ void seg_atomic(float ll, int img, int lane) {
    unsigned mask = __match_any_sync(0xffffffffu, img);
    int hi = 31 - __clz(mask);
    float v = ll;
#pragma unroll
    for (int off = 1; off < 32; off <<= 1) {
        float o = __shfl_down_sync(0xffffffffu, v, off);
        if (lane + off <= hi) v += o;
    }
    if (img >= 0 && lane == (__ffs(mask) - 1)) {
        atomicAdd(&g_img_sum[img], v);
        atomicAdd(&g_img_cnt[img], (float)__popc(mask));
    }
}

// ---------------- kernel 2: MLP + likelihood, 2 reflections/thread ----------------
__global__ __launch_bounds__(128) void refl_kernel(const float* __restrict__ metadata,
                                                   const float* __restrict__ W1,
                                                   const float* __restrict__ b1,
                                                   const float* __restrict__ W2,
                                                   const float* __restrict__ b2,
                                                   const float* __restrict__ iobs,
                                                   const float* __restrict__ sigiobs,
                                                   const int*   __restrict__ image_id,
                                                   const int*   __restrict__ miller_id,
                                                   float*       __restrict__ out) {
    // Packed-pair weight layout: every LDS.128 yields 2 ull (= 4 consecutive cols)
    __shared__ ulonglong2 sW1[128];  // W1: 16 rows x 32 floats = 128 x ulonglong2
    __shared__ ulonglong2 sW2[64];   // W2: 32 rows x  8 floats =  64 x ulonglong2
    __shared__ ull        sb1[16];   // b1 pairs (32 floats)
    __shared__ ull        sb2[4];    // b2 pairs (8 floats)

    int tid = threadIdx.x;
    sW1[tid] = ((const ulonglong2*)W1)[tid];
    if (tid < 64) sW2[tid] = ((const ulonglong2*)W2)[tid];
    if (tid < 16) sb1[tid] = ((const ull*)b1)[tid];
    if (tid < 4)  sb2[tid] = ((const ull*)b2)[tid];
    __syncthreads();

    int rA = blockIdx.x * 256 + tid;
    int rB = rA + 128;
    bool vA = rA < N_REFLNS;
    bool vB = rB < N_REFLNS;

    ull hA[16], hB[16];
#pragma unroll
    for (int j = 0; j < 16; j++) { hA[j] = sb1[j]; hB[j] = sb1[j]; }

    const float4* mpA = (const float4*)(metadata + (size_t)rA * D_META);
    const float4* mpB = (const float4*)(metadata + (size_t)rB * D_META);
    const float4 z4 = make_float4(0.f, 0.f, 0.f, 0.f);

    // ---- layer 1: h = meta @ W1 + b1 (weights LDS once, reused for A and B) ----
#pragma unroll
    for (int c = 0; c < 4; c++) {
        float4 ma = vA ? mpA[c] : z4;
        float4 mb = vB ? mpB[c] : z4;
        float mav[4] = {ma.x, ma.y, ma.z, ma.w};
        float mbv[4] = {mb.x, mb.y, mb.z, mb.w};
#pragma unroll
        for (int ii = 0; ii < 4; ii++) {
            int i = 4 * c + ii;
            ull aA = bcast2(mav[ii]);
            ull aB = bcast2(mbv[ii]);
#pragma unroll
            for (int q = 0; q < 8; q++) {
                ulonglong2 w = sW1[i * 8 + q];
                hA[2 * q]     = ffma2u(aA, w.x, hA[2 * q]);
                hA[2 * q + 1] = ffma2u(aA, w.y, hA[2 * q + 1]);
                hB[2 * q]     = ffma2u(aB, w.x, hB[2 * q]);
                hB[2 * q + 1] = ffma2u(aB, w.y, hB[2 * q + 1]);
            }
        }
    }

    // ---- layer 2: p = relu(h) @ W2 + b2 ----
    ull pA[4], pB[4];
#pragma unroll
    for (int k = 0; k < 4; k++) { pA[k] = sb2[k]; pB[k] = sb2[k]; }
#pragma unroll
    for (int up = 0; up < 16; up++) {
        // rows u0 = 2*up, u1 = 2*up+1 of W2, each row = 2 ulonglong2
        ulonglong2 w00 = sW2[4 * up + 0];   // row u0, outputs 0..3
        ulonglong2 w01 = sW2[4 * up + 1];   // row u0, outputs 4..7
        ulonglong2 w10 = sW2[4 * up + 2];   // row u1, outputs 0..3
        ulonglong2 w11 = sW2[4 * up + 3];   // row u1, outputs 4..7

        float2 ha = unpack2(hA[up]);
        float2 hb = unpack2(hB[up]);
        ull xA = bcast2(fmaxf(ha.x, 0.0f));
        ull yA = bcast2(fmaxf(ha.y, 0.0f));
        ull xB = bcast2(fmaxf(hb.x, 0.0f));
        ull yB = bcast2(fmaxf(hb.y, 0.0f));

        pA[0] = ffma2u(xA, w00.x, pA[0]); pA[1] = ffma2u(xA, w00.y, pA[1]);
        pA[2] = ffma2u(xA, w01.x, pA[2]); pA[3] = ffma2u(xA, w01.y, pA[3]);
        pA[0] = ffma2u(yA, w10.x, pA[0]); pA[1] = ffma2u(yA, w10.y, pA[1]);
        pA[2] = ffma2u(yA, w11.x, pA[2]); pA[3] = ffma2u(yA, w11.y, pA[3]);

        pB[0] = ffma2u(xB, w00.x, pB[0]); pB[1] = ffma2u(xB, w00.y, pB[1]);
        pB[2] = ffma2u(xB, w01.x, pB[2]); pB[3] = ffma2u(xB, w01.y, pB[3]);
        pB[0] = ffma2u(yB, w10.x, pB[0]); pB[1] = ffma2u(yB, w10.y, pB[1]);
        pB[2] = ffma2u(yB, w11.x, pB[2]); pB[3] = ffma2u(yB, w11.y, pB[3]);
    }

    int lane = tid & 31;
    float llA, llB; int imgA, imgB;
    epilogue(pA, rA, vA, iobs, sigiobs, image_id, miller_id, out, llA, imgA);
    epilogue(pB, rB, vB, iobs, sigiobs, image_id, miller_id, out, llB, imgB);
    seg_atomic(llA, imgA, lane);
    seg_atomic(llB, imgB, lane);
}

// ---------------- kernel 3: parallel finalize (8 blocks, last block writes) -----
__global__ __launch_bounds__(1024) void finalize_kernel(float* __restrict__ out) {
    int i = blockIdx.x * 1024 + threadIdx.x;
    float v = g_img_sum[i] * (1.0f / fmaxf(g_img_cnt[i], 1.0f));
#pragma unroll
    for (int off = 16; off; off >>= 1)
        v += __shfl_down_sync(0xffffffffu, v, off);
    __shared__ float wsum[32];
    int lane = threadIdx.x & 31, wid = threadIdx.x >> 5;
    if (lane == 0) wsum[wid] = v;
    __syncthreads();
    if (wid == 0) {
        float t = wsum[lane];
#pragma unroll
        for (int off = 16; off; off >>= 1)
            t += __shfl_down_sync(0xffffffffu, t, off);
        if (lane == 0) {
            atomicAdd(&g_ll_total, t);
            __threadfence();
            unsigned ticket = atomicAdd(&g_done, 1u);
            if (ticket == gridDim.x - 1) {
                float total = atomicAdd(&g_ll_total, 0.0f);  // fenced read of final sum
                out[N_REFLNS]     = -(total / (float)MC) / (float)N_IMAGES;
                out[N_REFLNS + 1] = g_kl_sum * (1.0f / (float)N_RAC);
            }
        }
    }
}

// ---------------- launch ----------------
extern "C" void kernel_launch(void* const* d_in, const int* in_sizes, int n_in,
                              void* d_out, int out_size) {
    const float* q_loc     = (const float*)d_in[0];
    const float* q_ls      = (const float*)d_in[1];
    const float* eps       = (const float*)d_in[2];
    const float* metadata  = (const float*)d_in[3];
    const float* W1        = (const float*)d_in[4];
    const float* b1        = (const float*)d_in[5];
    const float* W2        = (const float*)d_in[6];
    const float* b2        = (const float*)d_in[7];
    const float* iobs      = (const float*)d_in[8];
    const float* sigiobs   = (const float*)d_in[9];
    const int*   image_id  = (const int*)d_in[10];
    const int*   miller_id = (const int*)d_in[11];
    float* out = (float*)d_out;

    init_kernel<<<(N_IMAGES + 255) / 256, 256>>>();
    zkl_kernel<<<(N_RAC + 255) / 256, 256>>>(q_loc, q_ls, eps);
    refl_kernel<<<(N_REFLNS + 255) / 256, 128>>>(metadata, W1, b1, W2, b2,
                                                 iobs, sigiobs, image_id, miller_id, out);
    finalize_kernel<<<N_IMAGES / 1024, 1024>>>(out);
}